// round 1
// baseline (speedup 1.0000x reference)
#include <cuda_runtime.h>
#include <math.h>

// Problem constants
#define BB 256
#define TT 1000
#define NN 200
#define NII 7

// ALPHA = 0.02/0.1 ; noise scale = 0.15*sqrt(2*ALPHA)
#define ALPHA_F 0.2f
#define OMA_F 0.8f
#define NSC_F 0.0948683292f

// packed fp32x2 FMA: acc.lo += w.lo*ylo ; acc.hi += w.hi*yhi
__device__ __forceinline__ void ffma2(unsigned long long& acc, unsigned long long w,
                                      float ylo, float yhi) {
    asm("{\n\t"
        ".reg .b64 yy;\n\t"
        "mov.b64 yy, {%2, %3};\n\t"
        "fma.rn.f32x2 %0, %1, yy, %0;\n\t"
        "}"
        : "+l"(acc) : "l"(w), "f"(ylo), "f"(yhi));
}

__device__ __forceinline__ float hsum2(unsigned long long a) {
    float2 f;
    asm("mov.b64 {%0, %1}, %2;" : "=f"(f.x), "=f"(f.y) : "l"(a));
    return f.x + f.y;
}

__global__ void __launch_bounds__(256, 1)
rnn_persistent_kernel(const float* __restrict__ y0,
                      const float* __restrict__ u_seq,
                      const float* __restrict__ noise,
                      const float* __restrict__ W_in_raw,
                      const float* __restrict__ W_rec,
                      const float* __restrict__ b_rec,
                      const float* __restrict__ w_out,
                      const float* __restrict__ b_out,
                      float* __restrict__ out)
{
    __shared__ __align__(16) float y_s[2][2][NN];   // [buf][row][neuron]
    __shared__ float u_s[2][2][NII];                // [buf][row][input]

    const int tid = threadIdx.x;
    const int b0  = blockIdx.x * 2;
    const int b1  = b0 + 1;

    float* __restrict__ y_seq = out;                                        // (B,T,N)
    float* __restrict__ z_seq = out + (size_t)BB * TT * NN;                 // (B,T,1)
    float* __restrict__ y_fin = out + (size_t)BB * TT * NN + (size_t)BB*TT; // (B,N)

    const bool is_neuron = (tid <  NN);
    const bool is_z      = (tid == NN);
    const bool active    = (tid <= NN);

    // ---- register-resident weight row (200 fp32 = 100 x b64) ----
    unsigned long long w[NN / 2];
    float wia[NII];
    float brec = 0.f, bout = 0.f;
    float yold0 = 0.f, yold1 = 0.f;

    if (is_neuron) {
        const unsigned long long* wrow =
            reinterpret_cast<const unsigned long long*>(W_rec + (size_t)tid * NN);
        #pragma unroll
        for (int m = 0; m < NN / 2; ++m) w[m] = __ldg(&wrow[m]);
        #pragma unroll
        for (int i = 0; i < NII; ++i) wia[i] = fabsf(W_in_raw[tid * NII + i]);
        brec  = b_rec[tid];
        yold0 = y0[(size_t)b0 * NN + tid];
        yold1 = y0[(size_t)b1 * NN + tid];
        y_s[0][0][tid] = yold0;
        y_s[0][1][tid] = yold1;
    } else if (is_z) {
        const unsigned long long* wrow =
            reinterpret_cast<const unsigned long long*>(w_out);
        #pragma unroll
        for (int m = 0; m < NN / 2; ++m) w[m] = __ldg(&wrow[m]);
        bout = b_out[0];
    }
    if (tid < 2 * NII) {
        int bl = tid / NII, i = tid % NII;
        u_s[0][bl][i] = u_seq[((size_t)(b0 + bl) * TT + 0) * NII + i];
    }
    // noise for t=0
    float nz0 = 0.f, nz1 = 0.f;
    if (is_neuron) {
        nz0 = noise[((size_t)b0 * TT + 0) * NN + tid];
        nz1 = noise[((size_t)b1 * TT + 0) * NN + tid];
    }
    __syncthreads();

    int buf = 0;
    for (int t = 0; t < TT; ++t) {
        // ---- prefetch next step's noise / u (1 step of latency hiding) ----
        float nz0n = 0.f, nz1n = 0.f, un = 0.f;
        if (is_neuron && (t + 1 < TT)) {
            nz0n = __ldcg(&noise[((size_t)b0 * TT + (t + 1)) * NN + tid]);
            nz1n = __ldcg(&noise[((size_t)b1 * TT + (t + 1)) * NN + tid]);
        }
        if (tid < 2 * NII && (t + 1 < TT)) {
            int bl = tid / NII, i = tid % NII;
            un = __ldcg(&u_seq[((size_t)(b0 + bl) * TT + (t + 1)) * NII + i]);
        }

        if (active) {
            // ---- dot: pre[row] = y[row] . W[tid]  (packed f32x2 over k-pairs) ----
            const float4* Y0 = reinterpret_cast<const float4*>(y_s[buf][0]);
            const float4* Y1 = reinterpret_cast<const float4*>(y_s[buf][1]);
            unsigned long long a0 = 0ull, a1 = 0ull;
            #pragma unroll
            for (int m = 0; m < NN / 4; ++m) {
                float4 p = Y0[m];
                float4 q = Y1[m];
                ffma2(a0, w[2 * m],     p.x, p.y);
                ffma2(a0, w[2 * m + 1], p.z, p.w);
                ffma2(a1, w[2 * m],     q.x, q.y);
                ffma2(a1, w[2 * m + 1], q.z, q.w);
            }
            float pre0 = hsum2(a0);
            float pre1 = hsum2(a1);

            if (is_neuron) {
                // drive = |W_in| . u + b_rec (inline, avoids 400MB drive traffic)
                float dr0 = brec, dr1 = brec;
                #pragma unroll
                for (int i = 0; i < NII; ++i) {
                    dr0 = fmaf(wia[i], u_s[buf][0][i], dr0);
                    dr1 = fmaf(wia[i], u_s[buf][1][i], dr1);
                }
                float r0 = fmaxf(pre0 + dr0, 0.f);
                float r1 = fmaxf(pre1 + dr1, 0.f);
                float yn0 = fmaf(OMA_F, yold0, fmaf(ALPHA_F, r0, NSC_F * nz0));
                float yn1 = fmaf(OMA_F, yold1, fmaf(ALPHA_F, r1, NSC_F * nz1));
                y_seq[((size_t)b0 * TT + t) * NN + tid] = yn0;
                y_seq[((size_t)b1 * TT + t) * NN + tid] = yn1;
                yold0 = yn0; yold1 = yn1;
                y_s[buf ^ 1][0][tid] = yn0;
                y_s[buf ^ 1][1][tid] = yn1;
                nz0 = nz0n; nz1 = nz1n;
            } else {
                // z thread: dot was w_out . y_{t-1}  (y_s holds previous step's output)
                if (t >= 1) {
                    z_seq[(size_t)b0 * TT + (t - 1)] = 1.f / (1.f + expf(-(pre0 + bout)));
                    z_seq[(size_t)b1 * TT + (t - 1)] = 1.f / (1.f + expf(-(pre1 + bout)));
                }
            }
        }
        if (tid < 2 * NII && (t + 1 < TT)) {
            int bl = tid / NII, i = tid % NII;
            u_s[buf ^ 1][bl][i] = un;
        }
        __syncthreads();
        buf ^= 1;
    }

    // ---- tails ----
    if (is_neuron) {
        y_fin[(size_t)b0 * NN + tid] = yold0;
        y_fin[(size_t)b1 * NN + tid] = yold1;
    }
    if (is_z) {
        // final readout of y_{T-1} (now in y_s[buf])
        const float4* Y0 = reinterpret_cast<const float4*>(y_s[buf][0]);
        const float4* Y1 = reinterpret_cast<const float4*>(y_s[buf][1]);
        unsigned long long a0 = 0ull, a1 = 0ull;
        #pragma unroll
        for (int m = 0; m < NN / 4; ++m) {
            float4 p = Y0[m];
            float4 q = Y1[m];
            ffma2(a0, w[2 * m],     p.x, p.y);
            ffma2(a0, w[2 * m + 1], p.z, p.w);
            ffma2(a1, w[2 * m],     q.x, q.y);
            ffma2(a1, w[2 * m + 1], q.z, q.w);
        }
        z_seq[(size_t)b0 * TT + (TT - 1)] = 1.f / (1.f + expf(-(hsum2(a0) + bout)));
        z_seq[(size_t)b1 * TT + (TT - 1)] = 1.f / (1.f + expf(-(hsum2(a1) + bout)));
    }
}

extern "C" void kernel_launch(void* const* d_in, const int* in_sizes, int n_in,
                              void* d_out, int out_size) {
    const float* y0       = (const float*)d_in[0];
    const float* u_seq    = (const float*)d_in[1];
    const float* noise    = (const float*)d_in[2];
    const float* W_in_raw = (const float*)d_in[3];
    const float* W_rec    = (const float*)d_in[4];
    const float* b_rec    = (const float*)d_in[5];
    const float* w_out    = (const float*)d_in[6];
    const float* b_out    = (const float*)d_in[7];
    float* out = (float*)d_out;

    rnn_persistent_kernel<<<BB / 2, 256>>>(y0, u_seq, noise, W_in_raw, W_rec,
                                           b_rec, w_out, b_out, out);
}